// round 1
// baseline (speedup 1.0000x reference)
#include <cuda_runtime.h>
#include <stdint.h>

typedef unsigned long long u64;

#define M_UP   32768
#define N_DOWN 8192
#define C_OUT  128

// ---------------- device scratch (no allocations allowed) ----------------
__device__ float4 g_pts4[N_DOWN];                 // {x,y,z,|p|^2}
__device__ float  g_downf[N_DOWN * C_OUT];        // down linear output
__device__ int    g_knn_idx[3][M_UP];
__device__ float  g_knn_w[3][M_UP];

// ---------------- f32x2 helpers (sm_103a packed fp32) ----------------
__device__ __forceinline__ void fma2(u64& d, u64 a, u64 b) {
    asm("fma.rn.f32x2 %0, %1, %2, %0;" : "+l"(d) : "l"(a), "l"(b));
}
__device__ __forceinline__ u64 splat2(float s) {
    u64 d; unsigned int b = __float_as_uint(s);
    asm("mov.b64 %0, {%1, %1};" : "=l"(d) : "r"(b));
    return d;
}

// ---------------- pack down points with precomputed norms ----------------
__global__ void pack_points_kernel(const float* __restrict__ dp) {
    int i = blockIdx.x * blockDim.x + threadIdx.x;
    if (i < N_DOWN) {
        float x = dp[3*i], y = dp[3*i+1], z = dp[3*i+2];
        g_pts4[i] = make_float4(x, y, z, fmaf(x, x, fmaf(y, y, z*z)));
    }
}

// ---------------- brute-force KNN (k=3), one query per thread ----------------
#define KNN_TILE 2048
__global__ void __launch_bounds__(256) knn_kernel(const float* __restrict__ up_points) {
    __shared__ __align__(16) float4 tile[KNN_TILE];
    const int m = blockIdx.x * 256 + threadIdx.x;
    const float qx = up_points[3*m], qy = up_points[3*m+1], qz = up_points[3*m+2];
    const float qn = fmaf(qx, qx, fmaf(qy, qy, qz*qz));

    // scores s = |p|^2 - 2 q.p  (dist^2 minus constant qn: same ranking)
    float s0 = 3e38f, s1 = 3e38f, s2 = 3e38f;
    int   i0 = 0,     i1 = 0,     i2 = 0;

    for (int base = 0; base < N_DOWN; base += KNN_TILE) {
        __syncthreads();
        #pragma unroll
        for (int j = threadIdx.x; j < KNN_TILE; j += 256)
            tile[j] = g_pts4[base + j];
        __syncthreads();
        #pragma unroll 8
        for (int j = 0; j < KNN_TILE; j++) {
            float4 p = tile[j];
            float dot = fmaf(qx, p.x, fmaf(qy, p.y, qz * p.z));
            float s   = fmaf(-2.0f, dot, p.w);
            if (s < s2) {
                int idx = base + j;
                if (s < s1) {
                    s2 = s1; i2 = i1;
                    if (s < s0) { s1 = s0; i1 = i0; s0 = s; i0 = idx; }
                    else        { s1 = s;  i1 = idx; }
                } else { s2 = s; i2 = idx; }
            }
        }
    }
    // recover real squared distances, compute normalized inverse-distance weights
    float d0 = fmaxf(s0 + qn, 0.0f);
    float d1 = fmaxf(s1 + qn, 0.0f);
    float d2 = fmaxf(s2 + qn, 0.0f);
    float r0 = 1.0f / (d0 + 1e-8f);
    float r1 = 1.0f / (d1 + 1e-8f);
    float r2 = 1.0f / (d2 + 1e-8f);
    float inv = 1.0f / (r0 + r1 + r2);
    g_knn_idx[0][m] = i0; g_knn_idx[1][m] = i1; g_knn_idx[2][m] = i2;
    g_knn_w[0][m] = r0 * inv; g_knn_w[1][m] = r1 * inv; g_knn_w[2][m] = r2 * inv;
}

// ---------------- fp32 linear: out[M][128] = A[M][KTOT] @ W[128][KTOT]^T + b ----
// 8x8 per-thread micro-tile, f32x2 packed FMAs (32 FFMA2 per k-step per thread).
// FUSE: adds 3-NN inverse-distance interpolation of g_downf in the epilogue.
template<int BM, int KTOT, bool FUSE>
__global__ void __launch_bounds__(BM*2) linear_kernel(
    const float* __restrict__ A,
    const float* __restrict__ W,
    const float* __restrict__ bias,
    float* __restrict__ out)
{
    constexpr int BK   = 32;
    constexpr int NT   = BM * 2;       // threads: (BM/8) row-groups x 16 col-groups
    constexpr int ASTR = BM + 4;
    __shared__ __align__(16) float As[BK][ASTR];       // transposed A tile
    __shared__ __align__(16) float Ws[BK][C_OUT + 4];  // transposed W tile

    const int tid = threadIdx.x;
    const int tx  = tid & 15;          // col group (8 cols each)
    const int ty  = tid >> 4;          // row group (8 rows each)
    const int rowBase = blockIdx.x * BM;

    u64 acc[8][4];
    #pragma unroll
    for (int i = 0; i < 8; i++)
        #pragma unroll
        for (int j = 0; j < 4; j++) acc[i][j] = 0ull;

    for (int k0 = 0; k0 < KTOT; k0 += BK) {
        // A tile: [BM rows] x [BK k], stored k-major
        #pragma unroll
        for (int i = tid; i < BM * (BK/4); i += NT) {
            int r  = i >> 3;
            int kq = (i & 7) << 2;
            float4 v = *(const float4*)(A + (size_t)(rowBase + r) * KTOT + k0 + kq);
            As[kq+0][r] = v.x; As[kq+1][r] = v.y; As[kq+2][r] = v.z; As[kq+3][r] = v.w;
        }
        // W tile: [128 cols] x [BK k], stored k-major
        #pragma unroll
        for (int i = tid; i < C_OUT * (BK/4); i += NT) {
            int c  = i >> 3;
            int kq = (i & 7) << 2;
            float4 v = *(const float4*)(W + (size_t)c * KTOT + k0 + kq);
            Ws[kq+0][c] = v.x; Ws[kq+1][c] = v.y; Ws[kq+2][c] = v.z; Ws[kq+3][c] = v.w;
        }
        __syncthreads();
        #pragma unroll
        for (int k = 0; k < BK; k++) {
            float4 alo = *(const float4*)&As[k][ty*8];
            float4 ahi = *(const float4*)&As[k][ty*8 + 4];
            ulonglong2 w01 = *(const ulonglong2*)&Ws[k][tx*8];
            ulonglong2 w23 = *(const ulonglong2*)&Ws[k][tx*8 + 4];
            u64 wv[4] = {w01.x, w01.y, w23.x, w23.y};
            u64 a2[8];
            a2[0] = splat2(alo.x); a2[1] = splat2(alo.y);
            a2[2] = splat2(alo.z); a2[3] = splat2(alo.w);
            a2[4] = splat2(ahi.x); a2[5] = splat2(ahi.y);
            a2[6] = splat2(ahi.z); a2[7] = splat2(ahi.w);
            #pragma unroll
            for (int i = 0; i < 8; i++)
                #pragma unroll
                for (int j = 0; j < 4; j++)
                    fma2(acc[i][j], a2[i], wv[j]);
        }
        __syncthreads();
    }

    // ---------------- epilogue ----------------
    const int cb = tx * 8;
    float b[8];
    #pragma unroll
    for (int j = 0; j < 8; j++) b[j] = bias[cb + j];

    #pragma unroll
    for (int i = 0; i < 8; i++) {
        const int m = rowBase + ty*8 + i;
        float o[8];
        #pragma unroll
        for (int j = 0; j < 4; j++) {
            union { u64 u; float2 f; } cvt; cvt.u = acc[i][j];
            o[2*j]   = cvt.f.x + b[2*j];
            o[2*j+1] = cvt.f.y + b[2*j+1];
        }
        if (FUSE) {
            #pragma unroll
            for (int t = 0; t < 3; t++) {
                int   idx = g_knn_idx[t][m];
                float w   = g_knn_w[t][m];
                const float* fr = g_downf + (size_t)idx * C_OUT + cb;
                float4 glo = *(const float4*)fr;
                float4 ghi = *(const float4*)(fr + 4);
                o[0] = fmaf(w, glo.x, o[0]); o[1] = fmaf(w, glo.y, o[1]);
                o[2] = fmaf(w, glo.z, o[2]); o[3] = fmaf(w, glo.w, o[3]);
                o[4] = fmaf(w, ghi.x, o[4]); o[5] = fmaf(w, ghi.y, o[5]);
                o[6] = fmaf(w, ghi.z, o[6]); o[7] = fmaf(w, ghi.w, o[7]);
            }
        }
        *(float4*)(out + (size_t)m * C_OUT + cb)     = make_float4(o[0], o[1], o[2], o[3]);
        *(float4*)(out + (size_t)m * C_OUT + cb + 4) = make_float4(o[4], o[5], o[6], o[7]);
    }
}

// ---------------- launch ----------------
extern "C" void kernel_launch(void* const* d_in, const int* in_sizes, int n_in,
                              void* d_out, int out_size) {
    (void)in_sizes; (void)n_in; (void)out_size;
    const float* up_points     = (const float*)d_in[0];
    const float* up_features   = (const float*)d_in[1];
    const float* down_points   = (const float*)d_in[2];
    const float* down_features = (const float*)d_in[3];
    const float* W_up          = (const float*)d_in[4];
    const float* b_up          = (const float*)d_in[5];
    const float* W_down        = (const float*)d_in[6];
    const float* b_down        = (const float*)d_in[7];
    float* out = (float*)d_out;

    float* downf_ptr = nullptr;
    cudaGetSymbolAddress((void**)&downf_ptr, g_downf);

    pack_points_kernel<<<(N_DOWN + 255) / 256, 256>>>(down_points);
    linear_kernel<64, 256, false><<<N_DOWN / 64, 128>>>(down_features, W_down, b_down, downf_ptr);
    knn_kernel<<<M_UP / 256, 256>>>(up_points);
    linear_kernel<128, 128, true><<<M_UP / 128, 256>>>(up_features, W_up, b_up, out);
}

// round 4
// speedup vs baseline: 1.0003x; 1.0003x over previous
#include <cuda_runtime.h>
#include <stdint.h>

typedef unsigned long long u64;

#define M_UP   32768
#define N_DOWN 8192
#define C_OUT  128

#define NSPLIT 4
#define CHUNK  (N_DOWN / NSPLIT)   // 2048 points per chunk
#define CPAIRS (CHUNK / 2)         // 1024 pairs per chunk

// ---------------- device scratch (no allocations allowed) ----------------
// pair-packed SoA: g_pair[2*j] = {x(2j),x(2j+1),y(2j),y(2j+1)}
//                  g_pair[2*j+1] = {z(2j),z(2j+1),|p|^2(2j),|p|^2(2j+1)}
__device__ __align__(16) float4 g_pair[2 * (N_DOWN / 2)];
__device__ float  g_downf[N_DOWN * C_OUT];        // down linear output
__device__ int    g_knn_idx[3][M_UP];
__device__ float  g_knn_w[3][M_UP];
__device__ float  g_part_s[NSPLIT][3][M_UP];
__device__ int    g_part_i[NSPLIT][3][M_UP];

// ---------------- f32x2 helpers (sm_103a packed fp32) ----------------
__device__ __forceinline__ void fma2(u64& d, u64 a, u64 b) {
    asm("fma.rn.f32x2 %0, %1, %2, %0;" : "+l"(d) : "l"(a), "l"(b));
}
__device__ __forceinline__ u64 fma2v(u64 a, u64 b, u64 c) {
    u64 d; asm("fma.rn.f32x2 %0, %1, %2, %3;" : "=l"(d) : "l"(a), "l"(b), "l"(c));
    return d;
}
__device__ __forceinline__ u64 mul2v(u64 a, u64 b) {
    u64 d; asm("mul.rn.f32x2 %0, %1, %2;" : "=l"(d) : "l"(a), "l"(b));
    return d;
}
__device__ __forceinline__ u64 splat2(float s) {
    u64 d; unsigned int b = __float_as_uint(s);
    asm("mov.b64 %0, {%1, %1};" : "=l"(d) : "r"(b));
    return d;
}
union U64F2 { u64 u; float2 f; };

// ---------------- pack down points pairwise with precomputed norms --------
__global__ void pack_pairs_kernel(const float* __restrict__ dp) {
    int j = blockIdx.x * blockDim.x + threadIdx.x;   // pair index
    if (j < N_DOWN / 2) {
        int p0 = 2 * j, p1 = 2 * j + 1;
        float x0 = dp[3*p0], y0 = dp[3*p0+1], z0 = dp[3*p0+2];
        float x1 = dp[3*p1], y1 = dp[3*p1+1], z1 = dp[3*p1+2];
        float n0 = fmaf(x0, x0, fmaf(y0, y0, z0*z0));
        float n1 = fmaf(x1, x1, fmaf(y1, y1, z1*z1));
        g_pair[2*j]     = make_float4(x0, x1, y0, y1);
        g_pair[2*j + 1] = make_float4(z0, z1, n0, n1);
    }
}

// ---------------- top-3 insertion (rare slow path) ----------------
__device__ __forceinline__ void insert3(float s, int idx,
                                        float& s0, float& s1, float& s2,
                                        int& i0, int& i1, int& i2) {
    if (s < s2) {
        if (s < s1) {
            s2 = s1; i2 = i1;
            if (s < s0) { s1 = s0; i1 = i0; s0 = s; i0 = idx; }
            else        { s1 = s;  i1 = idx; }
        } else { s2 = s; i2 = idx; }
    }
}

// ---------------- split-N brute-force KNN (k=3) ----------------
// grid = (M/256, NSPLIT). One query per thread, one 2048-pt chunk per block.y.
__global__ void __launch_bounds__(256) knn_part_kernel(const float* __restrict__ up_points) {
    const int m = blockIdx.x * 256 + threadIdx.x;
    const int c = blockIdx.y;

    const float qx = up_points[3*m], qy = up_points[3*m+1], qz = up_points[3*m+2];
    const u64 qx2 = splat2(qx), qy2 = splat2(qy), qz2 = splat2(qz);
    const u64 m22 = splat2(-2.0f);

    float s0 = 3e38f, s1 = 3e38f, s2v = 3e38f;
    int   i0 = 0,     i1 = 0,     i2 = 0;

    const ulonglong2* __restrict__ P =
        (const ulonglong2*)&g_pair[2 * (c * CPAIRS)];
    const int gbase = c * CHUNK;

    #pragma unroll 16
    for (int j = 0; j < CPAIRS; j++) {
        ulonglong2 a = P[2*j];       // {px2, py2}
        ulonglong2 b = P[2*j + 1];   // {pz2, pw2}
        u64 t = mul2v(b.x, qz2);
        t = fma2v(a.y, qy2, t);
        t = fma2v(a.x, qx2, t);              // dot products (packed pair)
        U64F2 s; s.u = fma2v(t, m22, b.y);   // s = |p|^2 - 2 q.p
        float sA = s.f.x, sB = s.f.y;
        float smn = fminf(sA, sB);
        if (smn < s2v) {                     // rare
            int gi = gbase + 2*j;
            insert3(sA, gi,     s0, s1, s2v, i0, i1, i2);
            insert3(sB, gi + 1, s0, s1, s2v, i0, i1, i2);
        }
    }

    g_part_s[c][0][m] = s0; g_part_s[c][1][m] = s1; g_part_s[c][2][m] = s2v;
    g_part_i[c][0][m] = i0; g_part_i[c][1][m] = i1; g_part_i[c][2][m] = i2;
}

// ---------------- merge 4x3 candidates -> top-3 + weights ----------------
__global__ void __launch_bounds__(256) knn_merge_kernel(const float* __restrict__ up_points) {
    const int m = blockIdx.x * 256 + threadIdx.x;
    float s0 = 3e38f, s1 = 3e38f, s2v = 3e38f;
    int   i0 = 0,     i1 = 0,     i2 = 0;
    #pragma unroll
    for (int c = 0; c < NSPLIT; c++)
        #pragma unroll
        for (int t = 0; t < 3; t++)
            insert3(g_part_s[c][t][m], g_part_i[c][t][m], s0, s1, s2v, i0, i1, i2);

    const float qx = up_points[3*m], qy = up_points[3*m+1], qz = up_points[3*m+2];
    const float qn = fmaf(qx, qx, fmaf(qy, qy, qz*qz));
    float d0 = fmaxf(s0  + qn, 0.0f);
    float d1 = fmaxf(s1  + qn, 0.0f);
    float d2 = fmaxf(s2v + qn, 0.0f);
    float r0 = 1.0f / (d0 + 1e-8f);
    float r1 = 1.0f / (d1 + 1e-8f);
    float r2 = 1.0f / (d2 + 1e-8f);
    float inv = 1.0f / (r0 + r1 + r2);
    g_knn_idx[0][m] = i0; g_knn_idx[1][m] = i1; g_knn_idx[2][m] = i2;
    g_knn_w[0][m] = r0 * inv; g_knn_w[1][m] = r1 * inv; g_knn_w[2][m] = r2 * inv;
}

// ---------------- fp32 linear: out[M][128] = A[M][KTOT] @ W[128][KTOT]^T + b ----
template<int BM, int KTOT, bool FUSE>
__global__ void __launch_bounds__(BM*2) linear_kernel(
    const float* __restrict__ A,
    const float* __restrict__ W,
    const float* __restrict__ bias,
    float* __restrict__ out)
{
    constexpr int BK   = 32;
    constexpr int NT   = BM * 2;
    constexpr int ASTR = BM + 4;
    __shared__ __align__(16) float As[BK][ASTR];
    __shared__ __align__(16) float Ws[BK][C_OUT + 4];

    const int tid = threadIdx.x;
    const int tx  = tid & 15;
    const int ty  = tid >> 4;
    const int rowBase = blockIdx.x * BM;

    u64 acc[8][4];
    #pragma unroll
    for (int i = 0; i < 8; i++)
        #pragma unroll
        for (int j = 0; j < 4; j++) acc[i][j] = 0ull;

    for (int k0 = 0; k0 < KTOT; k0 += BK) {
        #pragma unroll
        for (int i = tid; i < BM * (BK/4); i += NT) {
            int r  = i >> 3;
            int kq = (i & 7) << 2;
            float4 v = *(const float4*)(A + (size_t)(rowBase + r) * KTOT + k0 + kq);
            As[kq+0][r] = v.x; As[kq+1][r] = v.y; As[kq+2][r] = v.z; As[kq+3][r] = v.w;
        }
        #pragma unroll
        for (int i = tid; i < C_OUT * (BK/4); i += NT) {
            int c  = i >> 3;
            int kq = (i & 7) << 2;
            float4 v = *(const float4*)(W + (size_t)c * KTOT + k0 + kq);
            Ws[kq+0][c] = v.x; Ws[kq+1][c] = v.y; Ws[kq+2][c] = v.z; Ws[kq+3][c] = v.w;
        }
        __syncthreads();
        #pragma unroll
        for (int k = 0; k < BK; k++) {
            float4 alo = *(const float4*)&As[k][ty*8];
            float4 ahi = *(const float4*)&As[k][ty*8 + 4];
            ulonglong2 w01 = *(const ulonglong2*)&Ws[k][tx*8];
            ulonglong2 w23 = *(const ulonglong2*)&Ws[k][tx*8 + 4];
            u64 wv[4] = {w01.x, w01.y, w23.x, w23.y};
            u64 a2[8];
            a2[0] = splat2(alo.x); a2[1] = splat2(alo.y);
            a2[2] = splat2(alo.z); a2[3] = splat2(alo.w);
            a2[4] = splat2(ahi.x); a2[5] = splat2(ahi.y);
            a2[6] = splat2(ahi.z); a2[7] = splat2(ahi.w);
            #pragma unroll
            for (int i = 0; i < 8; i++)
                #pragma unroll
                for (int j = 0; j < 4; j++)
                    fma2(acc[i][j], a2[i], wv[j]);
        }
        __syncthreads();
    }

    const int cb = tx * 8;
    float b[8];
    #pragma unroll
    for (int j = 0; j < 8; j++) b[j] = bias[cb + j];

    #pragma unroll
    for (int i = 0; i < 8; i++) {
        const int m = rowBase + ty*8 + i;
        float o[8];
        #pragma unroll
        for (int j = 0; j < 4; j++) {
            U64F2 cvt; cvt.u = acc[i][j];
            o[2*j]   = cvt.f.x + b[2*j];
            o[2*j+1] = cvt.f.y + b[2*j+1];
        }
        if (FUSE) {
            #pragma unroll
            for (int t = 0; t < 3; t++) {
                int   idx = g_knn_idx[t][m];
                float w   = g_knn_w[t][m];
                const float* fr = g_downf + (size_t)idx * C_OUT + cb;
                float4 glo = *(const float4*)fr;
                float4 ghi = *(const float4*)(fr + 4);
                o[0] = fmaf(w, glo.x, o[0]); o[1] = fmaf(w, glo.y, o[1]);
                o[2] = fmaf(w, glo.z, o[2]); o[3] = fmaf(w, glo.w, o[3]);
                o[4] = fmaf(w, ghi.x, o[4]); o[5] = fmaf(w, ghi.y, o[5]);
                o[6] = fmaf(w, ghi.z, o[6]); o[7] = fmaf(w, ghi.w, o[7]);
            }
        }
        *(float4*)(out + (size_t)m * C_OUT + cb)     = make_float4(o[0], o[1], o[2], o[3]);
        *(float4*)(out + (size_t)m * C_OUT + cb + 4) = make_float4(o[4], o[5], o[6], o[7]);
    }
}

// ---------------- launch ----------------
extern "C" void kernel_launch(void* const* d_in, const int* in_sizes, int n_in,
                              void* d_out, int out_size) {
    (void)in_sizes; (void)n_in; (void)out_size;
    const float* up_points     = (const float*)d_in[0];
    const float* up_features   = (const float*)d_in[1];
    const float* down_points   = (const float*)d_in[2];
    const float* down_features = (const float*)d_in[3];
    const float* W_up          = (const float*)d_in[4];
    const float* b_up          = (const float*)d_in[5];
    const float* W_down        = (const float*)d_in[6];
    const float* b_down        = (const float*)d_in[7];
    float* out = (float*)d_out;

    float* downf_ptr = nullptr;
    cudaGetSymbolAddress((void**)&downf_ptr, g_downf);

    pack_pairs_kernel<<<(N_DOWN/2 + 255) / 256, 256>>>(down_points);
    knn_part_kernel<<<dim3(M_UP / 256, NSPLIT), 256>>>(up_points);
    linear_kernel<64, 256, false><<<N_DOWN / 64, 128>>>(down_features, W_down, b_down, downf_ptr);
    knn_merge_kernel<<<M_UP / 256, 256>>>(up_points);
    linear_kernel<128, 128, true><<<M_UP / 128, 256>>>(up_features, W_up, b_up, out);
}

// round 5
// speedup vs baseline: 1.0007x; 1.0003x over previous
#include <cuda_runtime.h>
#include <stdint.h>

typedef unsigned long long u64;

#define M_UP   32768
#define N_DOWN 8192
#define C_OUT  128

#define GRID   32
#define NC     (GRID*GRID*GRID)
#define LOC    (-4.25f)
#define CELLH  (8.5f / GRID)
#define INVH   ((float)GRID / 8.5f)

// ---------------- device scratch (no allocations allowed) ----------------
__device__ int   g_cellcnt[NC + 1];
__device__ int   g_cellstart[NC + 1];
__device__ int   g_cellcur[NC];
__device__ int   g_qcnt[NC + 1];
__device__ int   g_qcur[NC];
__device__ __align__(16) float4 g_spts[N_DOWN];   // sorted points {x,y,z,|p|^2}
__device__ int   g_ptid[N_DOWN];                  // sorted pos -> original idx
__device__ int   g_qorder[M_UP];                  // sorted pos -> query idx
__device__ float g_downf[N_DOWN * C_OUT];
__device__ int   g_knn_idx[3][M_UP];
__device__ float g_knn_w[3][M_UP];

// ---------------- f32x2 helpers (sm_103a packed fp32) ----------------
__device__ __forceinline__ void fma2(u64& d, u64 a, u64 b) {
    asm("fma.rn.f32x2 %0, %1, %2, %0;" : "+l"(d) : "l"(a), "l"(b));
}
__device__ __forceinline__ u64 splat2(float s) {
    u64 d; unsigned int b = __float_as_uint(s);
    asm("mov.b64 %0, {%1, %1};" : "=l"(d) : "r"(b));
    return d;
}
union U64F2 { u64 u; float2 f; };

// ---------------- grid helpers ----------------
__device__ __forceinline__ int clampi(int v, int lo, int hi) {
    return v < lo ? lo : (v > hi ? hi : v);
}
__device__ __forceinline__ int cell_coord(float x) {
    return clampi((int)floorf((x - LOC) * INVH), 0, GRID - 1);
}
__device__ __forceinline__ unsigned mexpand5(unsigned v) {
    v &= 0x1F;
    v = (v | (v << 8)) & 0x100F;
    v = (v | (v << 4)) & 0x10C3;
    v = (v | (v << 2)) & 0x1249;
    return v;
}
__device__ __forceinline__ int morton3(int x, int y, int z) {
    return (int)(mexpand5(x) | (mexpand5(y) << 1) | (mexpand5(z) << 2));
}

// ---------------- grid build: zero / histogram / scan / scatter ----------
__global__ void zero_counts_kernel() {
    int i = blockIdx.x * blockDim.x + threadIdx.x;
    if (i < NC) { g_cellcnt[i] = 0; g_qcnt[i] = 0; }
}

__global__ void hist_kernel(const float* __restrict__ dp,
                            const float* __restrict__ qp) {
    int i = blockIdx.x * blockDim.x + threadIdx.x;
    if (i < N_DOWN) {
        int cx = cell_coord(dp[3*i]), cy = cell_coord(dp[3*i+1]), cz = cell_coord(dp[3*i+2]);
        atomicAdd(&g_cellcnt[(cz * GRID + cy) * GRID + cx], 1);
    } else if (i < N_DOWN + M_UP) {
        int m = i - N_DOWN;
        int cx = cell_coord(qp[3*m]), cy = cell_coord(qp[3*m+1]), cz = cell_coord(qp[3*m+2]);
        atomicAdd(&g_qcnt[morton3(cx, cy, cz)], 1);
    }
}

// one block, 1024 threads: exclusive scan of both count arrays (32 bins/thread)
__global__ void __launch_bounds__(1024) scan_kernel() {
    __shared__ int sh[1024];
    const int t = threadIdx.x;
    const int base = t * 32;

    // ---- points ----
    int loc[32]; int s = 0;
    #pragma unroll
    for (int i = 0; i < 32; i++) { loc[i] = s; s += g_cellcnt[base + i]; }
    sh[t] = s; __syncthreads();
    int inc = s;
    for (int d = 1; d < 1024; d <<= 1) {
        int add = (t >= d) ? sh[t - d] : 0; __syncthreads();
        sh[t] += add; inc = sh[t]; __syncthreads();
    }
    int off = inc - s;
    #pragma unroll
    for (int i = 0; i < 32; i++) {
        int v = off + loc[i];
        g_cellstart[base + i] = v;
        g_cellcur[base + i]   = v;
    }
    if (t == 1023) g_cellstart[NC] = off + s;
    __syncthreads();

    // ---- queries ----
    s = 0;
    #pragma unroll
    for (int i = 0; i < 32; i++) { loc[i] = s; s += g_qcnt[base + i]; }
    sh[t] = s; __syncthreads();
    inc = s;
    for (int d = 1; d < 1024; d <<= 1) {
        int add = (t >= d) ? sh[t - d] : 0; __syncthreads();
        sh[t] += add; inc = sh[t]; __syncthreads();
    }
    off = inc - s;
    #pragma unroll
    for (int i = 0; i < 32; i++) g_qcur[base + i] = off + loc[i];
}

__global__ void scatter_kernel(const float* __restrict__ dp,
                               const float* __restrict__ qp) {
    int i = blockIdx.x * blockDim.x + threadIdx.x;
    if (i < N_DOWN) {
        float x = dp[3*i], y = dp[3*i+1], z = dp[3*i+2];
        int cx = cell_coord(x), cy = cell_coord(y), cz = cell_coord(z);
        int pos = atomicAdd(&g_cellcur[(cz * GRID + cy) * GRID + cx], 1);
        g_spts[pos] = make_float4(x, y, z, fmaf(x, x, fmaf(y, y, z * z)));
        g_ptid[pos] = i;
    } else if (i < N_DOWN + M_UP) {
        int m = i - N_DOWN;
        int cx = cell_coord(qp[3*m]), cy = cell_coord(qp[3*m+1]), cz = cell_coord(qp[3*m+2]);
        int pos = atomicAdd(&g_qcur[morton3(cx, cy, cz)], 1);
        g_qorder[pos] = m;
    }
}

// ---------------- exact KNN via ring expansion over the grid ------------
__global__ void __launch_bounds__(256) knn_grid_kernel(const float* __restrict__ qp) {
    const int t = blockIdx.x * 256 + threadIdx.x;
    const int m = g_qorder[t];

    const float qx = qp[3*m], qy = qp[3*m+1], qz = qp[3*m+2];
    const float qn = fmaf(qx, qx, fmaf(qy, qy, qz * qz));

    const int cx = cell_coord(qx), cy = cell_coord(qy), cz = cell_coord(qz);
    const float fx = qx - (LOC + cx * CELLH);
    const float fy = qy - (LOC + cy * CELLH);
    const float fz = qz - (LOC + cz * CELLH);
    float gm = fmaxf(fmaxf(fmaxf(fx, CELLH - fx), fmaxf(fy, CELLH - fy)),
                     fmaxf(fz, CELLH - fz));

    float s0 = 3e38f, s1 = 3e38f, s2 = 3e38f;   // s = |p|^2 - 2 q.p  (d^2 - qn)
    int   i0 = 0,     i1 = 0,     i2 = 0;

    for (int R = 0; R < GRID; R++) {
        const int zlo = max(cz - R, 0), zhi = min(cz + R, GRID - 1);
        for (int z = zlo; z <= zhi; z++) {
            const bool zedge = (z == cz - R) || (z == cz + R);
            const int ylo = max(cy - R, 0), yhi = min(cy + R, GRID - 1);
            for (int y = ylo; y <= yhi; y++) {
                const bool yedge = (y == cy - R) || (y == cy + R);
                const int rowbase = (z * GRID + y) * GRID;
                int start, end;
                if (zedge || yedge) {
                    const int xlo = max(cx - R, 0), xhi = min(cx + R, GRID - 1);
                    start = g_cellstart[rowbase + xlo];
                    end   = g_cellstart[rowbase + xhi + 1];
                    for (int p = start; p < end; p++) {
                        float4 P = g_spts[p];
                        float s = fmaf(-2.0f,
                                       fmaf(qx, P.x, fmaf(qy, P.y, qz * P.z)), P.w);
                        bool b0 = s < s0, b1 = s < s1, b2 = s < s2;
                        float ns2 = b1 ? s1 : (b2 ? s : s2);
                        int   ni2 = b1 ? i1 : (b2 ? p : i2);
                        float ns1 = b0 ? s0 : (b1 ? s : s1);
                        int   ni1 = b0 ? i0 : (b1 ? p : i1);
                        s0 = b0 ? s : s0;  i0 = b0 ? p : i0;
                        s1 = ns1; i1 = ni1; s2 = ns2; i2 = ni2;
                    }
                } else {
                    // interior row: only x = cx-R and x = cx+R
                    #pragma unroll
                    for (int side = 0; side < 2; side++) {
                        int xc = side ? cx + R : cx - R;
                        if (xc < 0 || xc > GRID - 1) continue;
                        start = g_cellstart[rowbase + xc];
                        end   = g_cellstart[rowbase + xc + 1];
                        for (int p = start; p < end; p++) {
                            float4 P = g_spts[p];
                            float s = fmaf(-2.0f,
                                           fmaf(qx, P.x, fmaf(qy, P.y, qz * P.z)), P.w);
                            bool b0 = s < s0, b1 = s < s1, b2 = s < s2;
                            float ns2 = b1 ? s1 : (b2 ? s : s2);
                            int   ni2 = b1 ? i1 : (b2 ? p : i2);
                            float ns1 = b0 ? s0 : (b1 ? s : s1);
                            int   ni1 = b0 ? i0 : (b1 ? p : i1);
                            s0 = b0 ? s : s0;  i0 = b0 ? p : i0;
                            s1 = ns1; i1 = ni1; s2 = ns2; i2 = ni2;
                        }
                    }
                }
            }
        }
        // stop if every unvisited cell is provably farther than current 3rd-best
        float mind = (float)(R + 1) * CELLH - gm;
        if (mind > 0.0f && fmaf(mind, mind, -qn) >= s2) break;
    }

    float d0 = fmaxf(s0 + qn, 0.0f);
    float d1 = fmaxf(s1 + qn, 0.0f);
    float d2 = fmaxf(s2 + qn, 0.0f);
    float r0 = 1.0f / (d0 + 1e-8f);
    float r1 = 1.0f / (d1 + 1e-8f);
    float r2 = 1.0f / (d2 + 1e-8f);
    float inv = 1.0f / (r0 + r1 + r2);
    g_knn_idx[0][m] = g_ptid[i0];
    g_knn_idx[1][m] = g_ptid[i1];
    g_knn_idx[2][m] = g_ptid[i2];
    g_knn_w[0][m] = r0 * inv;
    g_knn_w[1][m] = r1 * inv;
    g_knn_w[2][m] = r2 * inv;
}

// ---------------- fp32 linear: out[M][128] = A[M][KTOT] @ W[128][KTOT]^T + b ----
template<int BM, int KTOT, bool FUSE>
__global__ void __launch_bounds__(BM*2) linear_kernel(
    const float* __restrict__ A,
    const float* __restrict__ W,
    const float* __restrict__ bias,
    float* __restrict__ out)
{
    constexpr int BK   = 32;
    constexpr int NT   = BM * 2;
    constexpr int ASTR = BM + 4;
    __shared__ __align__(16) float As[BK][ASTR];
    __shared__ __align__(16) float Ws[BK][C_OUT + 4];

    const int tid = threadIdx.x;
    const int tx  = tid & 15;
    const int ty  = tid >> 4;
    const int rowBase = blockIdx.x * BM;

    u64 acc[8][4];
    #pragma unroll
    for (int i = 0; i < 8; i++)
        #pragma unroll
        for (int j = 0; j < 4; j++) acc[i][j] = 0ull;

    for (int k0 = 0; k0 < KTOT; k0 += BK) {
        #pragma unroll
        for (int i = tid; i < BM * (BK/4); i += NT) {
            int r  = i >> 3;
            int kq = (i & 7) << 2;
            float4 v = *(const float4*)(A + (size_t)(rowBase + r) * KTOT + k0 + kq);
            As[kq+0][r] = v.x; As[kq+1][r] = v.y; As[kq+2][r] = v.z; As[kq+3][r] = v.w;
        }
        #pragma unroll
        for (int i = tid; i < C_OUT * (BK/4); i += NT) {
            int c  = i >> 3;
            int kq = (i & 7) << 2;
            float4 v = *(const float4*)(W + (size_t)c * KTOT + k0 + kq);
            Ws[kq+0][c] = v.x; Ws[kq+1][c] = v.y; Ws[kq+2][c] = v.z; Ws[kq+3][c] = v.w;
        }
        __syncthreads();
        #pragma unroll
        for (int k = 0; k < BK; k++) {
            float4 alo = *(const float4*)&As[k][ty*8];
            float4 ahi = *(const float4*)&As[k][ty*8 + 4];
            ulonglong2 w01 = *(const ulonglong2*)&Ws[k][tx*8];
            ulonglong2 w23 = *(const ulonglong2*)&Ws[k][tx*8 + 4];
            u64 wv[4] = {w01.x, w01.y, w23.x, w23.y};
            u64 a2[8];
            a2[0] = splat2(alo.x); a2[1] = splat2(alo.y);
            a2[2] = splat2(alo.z); a2[3] = splat2(alo.w);
            a2[4] = splat2(ahi.x); a2[5] = splat2(ahi.y);
            a2[6] = splat2(ahi.z); a2[7] = splat2(ahi.w);
            #pragma unroll
            for (int i = 0; i < 8; i++)
                #pragma unroll
                for (int j = 0; j < 4; j++)
                    fma2(acc[i][j], a2[i], wv[j]);
        }
        __syncthreads();
    }

    const int cb = tx * 8;
    float b[8];
    #pragma unroll
    for (int j = 0; j < 8; j++) b[j] = bias[cb + j];

    #pragma unroll
    for (int i = 0; i < 8; i++) {
        const int m = rowBase + ty*8 + i;
        float o[8];
        #pragma unroll
        for (int j = 0; j < 4; j++) {
            U64F2 cvt; cvt.u = acc[i][j];
            o[2*j]   = cvt.f.x + b[2*j];
            o[2*j+1] = cvt.f.y + b[2*j+1];
        }
        if (FUSE) {
            #pragma unroll
            for (int t = 0; t < 3; t++) {
                int   idx = g_knn_idx[t][m];
                float w   = g_knn_w[t][m];
                const float* fr = g_downf + (size_t)idx * C_OUT + cb;
                float4 glo = *(const float4*)fr;
                float4 ghi = *(const float4*)(fr + 4);
                o[0] = fmaf(w, glo.x, o[0]); o[1] = fmaf(w, glo.y, o[1]);
                o[2] = fmaf(w, glo.z, o[2]); o[3] = fmaf(w, glo.w, o[3]);
                o[4] = fmaf(w, ghi.x, o[4]); o[5] = fmaf(w, ghi.y, o[5]);
                o[6] = fmaf(w, ghi.z, o[6]); o[7] = fmaf(w, ghi.w, o[7]);
            }
        }
        *(float4*)(out + (size_t)m * C_OUT + cb)     = make_float4(o[0], o[1], o[2], o[3]);
        *(float4*)(out + (size_t)m * C_OUT + cb + 4) = make_float4(o[4], o[5], o[6], o[7]);
    }
}

// ---------------- launch ----------------
extern "C" void kernel_launch(void* const* d_in, const int* in_sizes, int n_in,
                              void* d_out, int out_size) {
    (void)in_sizes; (void)n_in; (void)out_size;
    const float* up_points     = (const float*)d_in[0];
    const float* up_features   = (const float*)d_in[1];
    const float* down_points   = (const float*)d_in[2];
    const float* down_features = (const float*)d_in[3];
    const float* W_up          = (const float*)d_in[4];
    const float* b_up          = (const float*)d_in[5];
    const float* W_down        = (const float*)d_in[6];
    const float* b_down        = (const float*)d_in[7];
    float* out = (float*)d_out;

    float* downf_ptr = nullptr;
    cudaGetSymbolAddress((void**)&downf_ptr, g_downf);

    zero_counts_kernel<<<(NC + 255) / 256, 256>>>();
    hist_kernel<<<(N_DOWN + M_UP + 255) / 256, 256>>>(down_points, up_points);
    scan_kernel<<<1, 1024>>>();
    scatter_kernel<<<(N_DOWN + M_UP + 255) / 256, 256>>>(down_points, up_points);
    linear_kernel<64, 256, false><<<N_DOWN / 64, 128>>>(down_features, W_down, b_down, downf_ptr);
    knn_grid_kernel<<<M_UP / 256, 256>>>(up_points);
    linear_kernel<128, 128, true><<<M_UP / 128, 256>>>(up_features, W_up, b_up, out);
}

// round 6
// speedup vs baseline: 1.3260x; 1.3251x over previous
#include <cuda_runtime.h>
#include <stdint.h>

typedef unsigned long long u64;

#define M_UP   32768
#define N_DOWN 8192
#define C_OUT  128

#define GRID   32
#define NC     (GRID*GRID*GRID)
#define LOC    (-4.25f)
#define CELLH  (8.5f / GRID)
#define INVH   ((float)GRID / 8.5f)

#define SKEW(i) ((i) + ((i) >> 5))
#define SCAN_SMEM_INTS (SKEW(NC) + 32 + 1024)
#define SCAN_SMEM_BYTES (SCAN_SMEM_INTS * 4)

// ---------------- device scratch (no allocations allowed) ----------------
__device__ int   g_cellcnt[NC];        // zero-initialized at load; re-zeroed by lin_up
__device__ int   g_qcnt[NC];           // "
__device__ int   g_cellstart[NC + 1];
__device__ int   g_cellcur[NC];
__device__ int   g_qcur[NC];
__device__ __align__(16) float4 g_spts[N_DOWN];   // sorted points {x,y,z,|p|^2}
__device__ int   g_ptid[N_DOWN];                  // sorted pos -> original idx
__device__ int   g_qorder[M_UP];                  // sorted pos -> query idx
__device__ float g_downf[N_DOWN * C_OUT];
__device__ int   g_knn_idx[3][M_UP];
__device__ float g_knn_w[3][M_UP];

// ---------------- f32x2 helpers (sm_103a packed fp32) ----------------
__device__ __forceinline__ void fma2(u64& d, u64 a, u64 b) {
    asm("fma.rn.f32x2 %0, %1, %2, %0;" : "+l"(d) : "l"(a), "l"(b));
}
__device__ __forceinline__ u64 splat2(float s) {
    u64 d; unsigned int b = __float_as_uint(s);
    asm("mov.b64 %0, {%1, %1};" : "=l"(d) : "r"(b));
    return d;
}
union U64F2 { u64 u; float2 f; };

// ---------------- grid helpers ----------------
__device__ __forceinline__ int clampi(int v, int lo, int hi) {
    return v < lo ? lo : (v > hi ? hi : v);
}
__device__ __forceinline__ int cell_coord(float x) {
    return clampi((int)floorf((x - LOC) * INVH), 0, GRID - 1);
}
__device__ __forceinline__ unsigned mexpand5(unsigned v) {
    v &= 0x1F;
    v = (v | (v << 8)) & 0x100F;
    v = (v | (v << 4)) & 0x10C3;
    v = (v | (v << 2)) & 0x1249;
    return v;
}
__device__ __forceinline__ int morton3(int x, int y, int z) {
    return (int)(mexpand5(x) | (mexpand5(y) << 1) | (mexpand5(z) << 2));
}

// ---------------- histogram (counts zeroed by previous lin_up / load-init) --
__global__ void hist_kernel(const float* __restrict__ dp,
                            const float* __restrict__ qp) {
    int i = blockIdx.x * blockDim.x + threadIdx.x;
    if (i < N_DOWN) {
        int cx = cell_coord(dp[3*i]), cy = cell_coord(dp[3*i+1]), cz = cell_coord(dp[3*i+2]);
        atomicAdd(&g_cellcnt[(cz * GRID + cy) * GRID + cx], 1);
    } else if (i < N_DOWN + M_UP) {
        int m = i - N_DOWN;
        int cx = cell_coord(qp[3*m]), cy = cell_coord(qp[3*m+1]), cz = cell_coord(qp[3*m+2]);
        atomicAdd(&g_qcnt[morton3(cx, cy, cz)], 1);
    }
}

// one block, 1024 threads: exclusive scan of both count arrays.
// Coalesced gmem<->smem staging; skewed smem layout kills bank conflicts.
__global__ void __launch_bounds__(1024) scan_kernel() {
    extern __shared__ int dsh[];
    int* tile = dsh;                       // SKEW(NC) ints
    int* bsum = dsh + SKEW(NC) + 32;       // 1024 ints
    const int t = threadIdx.x;
    const int base = t * 32;

    #pragma unroll 1
    for (int pass = 0; pass < 2; pass++) {
        const int* src = pass ? g_qcnt : g_cellcnt;
        for (int j = t; j < NC; j += 1024) tile[SKEW(j)] = src[j];
        __syncthreads();

        int loc[32]; int s = 0;
        #pragma unroll
        for (int i = 0; i < 32; i++) { loc[i] = s; s += tile[SKEW(base + i)]; }
        bsum[t] = s;
        __syncthreads();
        for (int d = 1; d < 1024; d <<= 1) {
            int a = (t >= d) ? bsum[t - d] : 0;
            __syncthreads();
            bsum[t] += a;
            __syncthreads();
        }
        int off = bsum[t] - s;
        #pragma unroll
        for (int i = 0; i < 32; i++) tile[SKEW(base + i)] = off + loc[i];
        __syncthreads();

        if (pass == 0) {
            for (int j = t; j < NC; j += 1024) {
                int v = tile[SKEW(j)];
                g_cellstart[j] = v;
                g_cellcur[j]   = v;
            }
            if (t == 1023) g_cellstart[NC] = off + s;
        } else {
            for (int j = t; j < NC; j += 1024) g_qcur[j] = tile[SKEW(j)];
        }
        __syncthreads();
    }
}

__global__ void scatter_kernel(const float* __restrict__ dp,
                               const float* __restrict__ qp) {
    int i = blockIdx.x * blockDim.x + threadIdx.x;
    if (i < N_DOWN) {
        float x = dp[3*i], y = dp[3*i+1], z = dp[3*i+2];
        int cx = cell_coord(x), cy = cell_coord(y), cz = cell_coord(z);
        int pos = atomicAdd(&g_cellcur[(cz * GRID + cy) * GRID + cx], 1);
        g_spts[pos] = make_float4(x, y, z, fmaf(x, x, fmaf(y, y, z * z)));
        g_ptid[pos] = i;
    } else if (i < N_DOWN + M_UP) {
        int m = i - N_DOWN;
        int cx = cell_coord(qp[3*m]), cy = cell_coord(qp[3*m+1]), cz = cell_coord(qp[3*m+2]);
        int pos = atomicAdd(&g_qcur[morton3(cx, cy, cz)], 1);
        g_qorder[pos] = m;
    }
}

// ---------------- exact KNN via ring expansion over the grid ------------
__global__ void __launch_bounds__(256) knn_grid_kernel(const float* __restrict__ qp) {
    const int t = blockIdx.x * 256 + threadIdx.x;
    const int m = g_qorder[t];

    const float qx = qp[3*m], qy = qp[3*m+1], qz = qp[3*m+2];
    const float qn = fmaf(qx, qx, fmaf(qy, qy, qz * qz));

    const int cx = cell_coord(qx), cy = cell_coord(qy), cz = cell_coord(qz);
    const float fx = qx - (LOC + cx * CELLH);
    const float fy = qy - (LOC + cy * CELLH);
    const float fz = qz - (LOC + cz * CELLH);
    float gm = fmaxf(fmaxf(fmaxf(fx, CELLH - fx), fmaxf(fy, CELLH - fy)),
                     fmaxf(fz, CELLH - fz));

    float s0 = 3e38f, s1 = 3e38f, s2 = 3e38f;   // s = |p|^2 - 2 q.p  (d^2 - qn)
    int   i0 = 0,     i1 = 0,     i2 = 0;

    for (int R = 0; R < GRID; R++) {
        const int zlo = max(cz - R, 0), zhi = min(cz + R, GRID - 1);
        for (int z = zlo; z <= zhi; z++) {
            const bool zedge = (z == cz - R) || (z == cz + R);
            const int ylo = max(cy - R, 0), yhi = min(cy + R, GRID - 1);
            for (int y = ylo; y <= yhi; y++) {
                const bool yedge = (y == cy - R) || (y == cy + R);
                const int rowbase = (z * GRID + y) * GRID;
                int start, end;
                if (zedge || yedge) {
                    const int xlo = max(cx - R, 0), xhi = min(cx + R, GRID - 1);
                    start = g_cellstart[rowbase + xlo];
                    end   = g_cellstart[rowbase + xhi + 1];
                    for (int p = start; p < end; p++) {
                        float4 P = g_spts[p];
                        float s = fmaf(-2.0f,
                                       fmaf(qx, P.x, fmaf(qy, P.y, qz * P.z)), P.w);
                        bool b0 = s < s0, b1 = s < s1, b2 = s < s2;
                        float ns2 = b1 ? s1 : (b2 ? s : s2);
                        int   ni2 = b1 ? i1 : (b2 ? p : i2);
                        float ns1 = b0 ? s0 : (b1 ? s : s1);
                        int   ni1 = b0 ? i0 : (b1 ? p : i1);
                        s0 = b0 ? s : s0;  i0 = b0 ? p : i0;
                        s1 = ns1; i1 = ni1; s2 = ns2; i2 = ni2;
                    }
                } else {
                    #pragma unroll
                    for (int side = 0; side < 2; side++) {
                        int xc = side ? cx + R : cx - R;
                        if (xc < 0 || xc > GRID - 1) continue;
                        start = g_cellstart[rowbase + xc];
                        end   = g_cellstart[rowbase + xc + 1];
                        for (int p = start; p < end; p++) {
                            float4 P = g_spts[p];
                            float s = fmaf(-2.0f,
                                           fmaf(qx, P.x, fmaf(qy, P.y, qz * P.z)), P.w);
                            bool b0 = s < s0, b1 = s < s1, b2 = s < s2;
                            float ns2 = b1 ? s1 : (b2 ? s : s2);
                            int   ni2 = b1 ? i1 : (b2 ? p : i2);
                            float ns1 = b0 ? s0 : (b1 ? s : s1);
                            int   ni1 = b0 ? i0 : (b1 ? p : i1);
                            s0 = b0 ? s : s0;  i0 = b0 ? p : i0;
                            s1 = ns1; i1 = ni1; s2 = ns2; i2 = ni2;
                        }
                    }
                }
            }
        }
        float mind = (float)(R + 1) * CELLH - gm;
        if (mind > 0.0f && fmaf(mind, mind, -qn) >= s2) break;
    }

    float d0 = fmaxf(s0 + qn, 0.0f);
    float d1 = fmaxf(s1 + qn, 0.0f);
    float d2 = fmaxf(s2 + qn, 0.0f);
    float r0 = 1.0f / (d0 + 1e-8f);
    float r1 = 1.0f / (d1 + 1e-8f);
    float r2 = 1.0f / (d2 + 1e-8f);
    float inv = 1.0f / (r0 + r1 + r2);
    g_knn_idx[0][m] = g_ptid[i0];
    g_knn_idx[1][m] = g_ptid[i1];
    g_knn_idx[2][m] = g_ptid[i2];
    g_knn_w[0][m] = r0 * inv;
    g_knn_w[1][m] = r1 * inv;
    g_knn_w[2][m] = r2 * inv;
}

// ---------------- fp32 linear: out[M][128] = A[M][KTOT] @ W[128][KTOT]^T + b ----
// FUSE also re-zeros the grid count arrays for the next replay.
template<int BM, int KTOT, bool FUSE>
__global__ void __launch_bounds__(BM*2) linear_kernel(
    const float* __restrict__ A,
    const float* __restrict__ W,
    const float* __restrict__ bias,
    float* __restrict__ out)
{
    constexpr int BK   = 32;
    constexpr int NT   = BM * 2;
    constexpr int ASTR = BM + 4;
    __shared__ __align__(16) float As[BK][ASTR];
    __shared__ __align__(16) float Ws[BK][C_OUT + 4];

    const int tid = threadIdx.x;
    const int tx  = tid & 15;
    const int ty  = tid >> 4;
    const int rowBase = blockIdx.x * BM;

    if (FUSE) {
        int g = blockIdx.x * NT + tid;
        if (g < NC) { g_cellcnt[g] = 0; g_qcnt[g] = 0; }
    }

    u64 acc[8][4];
    #pragma unroll
    for (int i = 0; i < 8; i++)
        #pragma unroll
        for (int j = 0; j < 4; j++) acc[i][j] = 0ull;

    for (int k0 = 0; k0 < KTOT; k0 += BK) {
        #pragma unroll
        for (int i = tid; i < BM * (BK/4); i += NT) {
            int r  = i >> 3;
            int kq = (i & 7) << 2;
            float4 v = *(const float4*)(A + (size_t)(rowBase + r) * KTOT + k0 + kq);
            As[kq+0][r] = v.x; As[kq+1][r] = v.y; As[kq+2][r] = v.z; As[kq+3][r] = v.w;
        }
        #pragma unroll
        for (int i = tid; i < C_OUT * (BK/4); i += NT) {
            int c  = i >> 3;
            int kq = (i & 7) << 2;
            float4 v = *(const float4*)(W + (size_t)c * KTOT + k0 + kq);
            Ws[kq+0][c] = v.x; Ws[kq+1][c] = v.y; Ws[kq+2][c] = v.z; Ws[kq+3][c] = v.w;
        }
        __syncthreads();
        #pragma unroll
        for (int k = 0; k < BK; k++) {
            float4 alo = *(const float4*)&As[k][ty*8];
            float4 ahi = *(const float4*)&As[k][ty*8 + 4];
            ulonglong2 w01 = *(const ulonglong2*)&Ws[k][tx*8];
            ulonglong2 w23 = *(const ulonglong2*)&Ws[k][tx*8 + 4];
            u64 wv[4] = {w01.x, w01.y, w23.x, w23.y};
            u64 a2[8];
            a2[0] = splat2(alo.x); a2[1] = splat2(alo.y);
            a2[2] = splat2(alo.z); a2[3] = splat2(alo.w);
            a2[4] = splat2(ahi.x); a2[5] = splat2(ahi.y);
            a2[6] = splat2(ahi.z); a2[7] = splat2(ahi.w);
            #pragma unroll
            for (int i = 0; i < 8; i++)
                #pragma unroll
                for (int j = 0; j < 4; j++)
                    fma2(acc[i][j], a2[i], wv[j]);
        }
        __syncthreads();
    }

    const int cb = tx * 8;
    float b[8];
    #pragma unroll
    for (int j = 0; j < 8; j++) b[j] = bias[cb + j];

    #pragma unroll
    for (int i = 0; i < 8; i++) {
        const int m = rowBase + ty*8 + i;
        float o[8];
        #pragma unroll
        for (int j = 0; j < 4; j++) {
            U64F2 cvt; cvt.u = acc[i][j];
            o[2*j]   = cvt.f.x + b[2*j];
            o[2*j+1] = cvt.f.y + b[2*j+1];
        }
        if (FUSE) {
            #pragma unroll
            for (int t = 0; t < 3; t++) {
                int   idx = g_knn_idx[t][m];
                float w   = g_knn_w[t][m];
                const float* fr = g_downf + (size_t)idx * C_OUT + cb;
                float4 glo = *(const float4*)fr;
                float4 ghi = *(const float4*)(fr + 4);
                o[0] = fmaf(w, glo.x, o[0]); o[1] = fmaf(w, glo.y, o[1]);
                o[2] = fmaf(w, glo.z, o[2]); o[3] = fmaf(w, glo.w, o[3]);
                o[4] = fmaf(w, ghi.x, o[4]); o[5] = fmaf(w, ghi.y, o[5]);
                o[6] = fmaf(w, ghi.z, o[6]); o[7] = fmaf(w, ghi.w, o[7]);
            }
        }
        *(float4*)(out + (size_t)m * C_OUT + cb)     = make_float4(o[0], o[1], o[2], o[3]);
        *(float4*)(out + (size_t)m * C_OUT + cb + 4) = make_float4(o[4], o[5], o[6], o[7]);
    }
}

// ---------------- launch ----------------
// Order matters: ncu deterministically profiles the 4th launch -> knn_grid.
extern "C" void kernel_launch(void* const* d_in, const int* in_sizes, int n_in,
                              void* d_out, int out_size) {
    (void)in_sizes; (void)n_in; (void)out_size;
    const float* up_points     = (const float*)d_in[0];
    const float* up_features   = (const float*)d_in[1];
    const float* down_points   = (const float*)d_in[2];
    const float* down_features = (const float*)d_in[3];
    const float* W_up          = (const float*)d_in[4];
    const float* b_up          = (const float*)d_in[5];
    const float* W_down        = (const float*)d_in[6];
    const float* b_down        = (const float*)d_in[7];
    float* out = (float*)d_out;

    float* downf_ptr = nullptr;
    cudaGetSymbolAddress((void**)&downf_ptr, g_downf);
    cudaFuncSetAttribute(scan_kernel, cudaFuncAttributeMaxDynamicSharedMemorySize,
                         SCAN_SMEM_BYTES);

    hist_kernel<<<(N_DOWN + M_UP + 255) / 256, 256>>>(down_points, up_points);      // 1
    scan_kernel<<<1, 1024, SCAN_SMEM_BYTES>>>();                                     // 2
    scatter_kernel<<<(N_DOWN + M_UP + 255) / 256, 256>>>(down_points, up_points);    // 3
    knn_grid_kernel<<<M_UP / 256, 256>>>(up_points);                                 // 4 <- profiled
    linear_kernel<64, 256, false><<<N_DOWN / 64, 128>>>(down_features, W_down, b_down, downf_ptr); // 5
    linear_kernel<64, 128, true><<<M_UP / 64, 128>>>(up_features, W_up, b_up, out);  // 6
}

// round 7
// speedup vs baseline: 1.6146x; 1.2177x over previous
#include <cuda_runtime.h>
#include <stdint.h>

typedef unsigned long long u64;

#define M_UP   32768
#define N_DOWN 8192
#define C_OUT  128

#define GRID   32
#define NC     (GRID*GRID*GRID)
#define LOC    (-4.25f)
#define CELLH  (8.5f / GRID)
#define INVH   ((float)GRID / 8.5f)

#define SKEW(i) ((i) + ((i) >> 5))
#define SCAN_SMEM_INTS (SKEW(NC) + 32 + 1024)
#define SCAN_SMEM_BYTES (SCAN_SMEM_INTS * 4)

#define QPB 64   // queries per knn block (x4 splits = 256 threads)

// ---------------- device scratch (no allocations allowed) ----------------
__device__ int   g_cellcnt[NC];        // zero-initialized at load; re-zeroed by lin_up
__device__ int   g_qcnt[NC];           // "
__device__ int   g_cellstart[NC + 1];
__device__ int   g_cellcur[NC];
__device__ int   g_qcur[NC];
__device__ __align__(16) float4 g_spts[N_DOWN];   // sorted points {x,y,z,|p|^2}
__device__ int   g_ptid[N_DOWN];                  // sorted pos -> original idx
__device__ int   g_qorder[M_UP];                  // sorted pos -> query idx
__device__ float g_downf[N_DOWN * C_OUT];
__device__ int   g_knn_idx[3][M_UP];
__device__ float g_knn_w[3][M_UP];

// ---------------- f32x2 helpers (sm_103a packed fp32) ----------------
__device__ __forceinline__ void fma2(u64& d, u64 a, u64 b) {
    asm("fma.rn.f32x2 %0, %1, %2, %0;" : "+l"(d) : "l"(a), "l"(b));
}
__device__ __forceinline__ u64 splat2(float s) {
    u64 d; unsigned int b = __float_as_uint(s);
    asm("mov.b64 %0, {%1, %1};" : "=l"(d) : "r"(b));
    return d;
}
union U64F2 { u64 u; float2 f; };

// ---------------- grid helpers ----------------
__device__ __forceinline__ int clampi(int v, int lo, int hi) {
    return v < lo ? lo : (v > hi ? hi : v);
}
__device__ __forceinline__ int cell_coord(float x) {
    return clampi((int)floorf((x - LOC) * INVH), 0, GRID - 1);
}
__device__ __forceinline__ unsigned mexpand5(unsigned v) {
    v &= 0x1F;
    v = (v | (v << 8)) & 0x100F;
    v = (v | (v << 4)) & 0x10C3;
    v = (v | (v << 2)) & 0x1249;
    return v;
}
__device__ __forceinline__ int morton3(int x, int y, int z) {
    return (int)(mexpand5(x) | (mexpand5(y) << 1) | (mexpand5(z) << 2));
}

// branchless top-3 insert (pred-as-data SELs, no BSSY)
__device__ __forceinline__ void bins3(float s, int p,
                                      float& s0, float& s1, float& s2,
                                      int& i0, int& i1, int& i2) {
    bool b0 = s < s0, b1 = s < s1, b2 = s < s2;
    float ns2 = b1 ? s1 : (b2 ? s : s2);
    int   ni2 = b1 ? i1 : (b2 ? p : i2);
    float ns1 = b0 ? s0 : (b1 ? s : s1);
    int   ni1 = b0 ? i0 : (b1 ? p : i1);
    s0 = b0 ? s : s0;  i0 = b0 ? p : i0;
    s1 = ns1; i1 = ni1; s2 = ns2; i2 = ni2;
}

// ---------------- histogram (counts zeroed by previous lin_up / load-init) --
__global__ void hist_kernel(const float* __restrict__ dp,
                            const float* __restrict__ qp) {
    int i = blockIdx.x * blockDim.x + threadIdx.x;
    if (i < N_DOWN) {
        int cx = cell_coord(dp[3*i]), cy = cell_coord(dp[3*i+1]), cz = cell_coord(dp[3*i+2]);
        atomicAdd(&g_cellcnt[(cz * GRID + cy) * GRID + cx], 1);
    } else if (i < N_DOWN + M_UP) {
        int m = i - N_DOWN;
        int cx = cell_coord(qp[3*m]), cy = cell_coord(qp[3*m+1]), cz = cell_coord(qp[3*m+2]);
        atomicAdd(&g_qcnt[morton3(cx, cy, cz)], 1);
    }
}

// one block, 1024 threads: exclusive scan of both count arrays (coalesced staging)
__global__ void __launch_bounds__(1024) scan_kernel() {
    extern __shared__ int dsh[];
    int* tile = dsh;
    int* bsum = dsh + SKEW(NC) + 32;
    const int t = threadIdx.x;
    const int base = t * 32;

    #pragma unroll 1
    for (int pass = 0; pass < 2; pass++) {
        const int* src = pass ? g_qcnt : g_cellcnt;
        for (int j = t; j < NC; j += 1024) tile[SKEW(j)] = src[j];
        __syncthreads();

        int loc[32]; int s = 0;
        #pragma unroll
        for (int i = 0; i < 32; i++) { loc[i] = s; s += tile[SKEW(base + i)]; }
        bsum[t] = s;
        __syncthreads();
        for (int d = 1; d < 1024; d <<= 1) {
            int a = (t >= d) ? bsum[t - d] : 0;
            __syncthreads();
            bsum[t] += a;
            __syncthreads();
        }
        int off = bsum[t] - s;
        #pragma unroll
        for (int i = 0; i < 32; i++) tile[SKEW(base + i)] = off + loc[i];
        __syncthreads();

        if (pass == 0) {
            for (int j = t; j < NC; j += 1024) {
                int v = tile[SKEW(j)];
                g_cellstart[j] = v;
                g_cellcur[j]   = v;
            }
            if (t == 1023) g_cellstart[NC] = off + s;
        } else {
            for (int j = t; j < NC; j += 1024) g_qcur[j] = tile[SKEW(j)];
        }
        __syncthreads();
    }
}

__global__ void scatter_kernel(const float* __restrict__ dp,
                               const float* __restrict__ qp) {
    int i = blockIdx.x * blockDim.x + threadIdx.x;
    if (i < N_DOWN) {
        float x = dp[3*i], y = dp[3*i+1], z = dp[3*i+2];
        int cx = cell_coord(x), cy = cell_coord(y), cz = cell_coord(z);
        int pos = atomicAdd(&g_cellcur[(cz * GRID + cy) * GRID + cx], 1);
        g_spts[pos] = make_float4(x, y, z, fmaf(x, x, fmaf(y, y, z * z)));
        g_ptid[pos] = i;
    } else if (i < N_DOWN + M_UP) {
        int m = i - N_DOWN;
        int cx = cell_coord(qp[3*m]), cy = cell_coord(qp[3*m+1]), cz = cell_coord(qp[3*m+2]);
        int pos = atomicAdd(&g_qcur[morton3(cx, cy, cz)], 1);
        g_qorder[pos] = m;
    }
}

// ---------------- exact KNN: 4 threads per query (rows split by z,y parity) ----
// Layout split-major: warp lanes = 32 Morton-adjacent queries on the SAME split.
__global__ void __launch_bounds__(256) knn_grid_kernel(const float* __restrict__ qp) {
    __shared__ float sh_s[256][3];
    __shared__ int   sh_i[256][3];

    const int tl    = threadIdx.x;
    const int split = tl >> 6;          // 0..3
    const int qslot = tl & 63;          // 0..63
    const int sz    = split & 1;
    const int sy    = split >> 1;
    const int t     = blockIdx.x * QPB + qslot;
    const int m     = g_qorder[t];

    const float qx = qp[3*m], qy = qp[3*m+1], qz = qp[3*m+2];
    const float qn = fmaf(qx, qx, fmaf(qy, qy, qz * qz));

    const int cx = cell_coord(qx), cy = cell_coord(qy), cz = cell_coord(qz);
    const float fx = qx - (LOC + cx * CELLH);
    const float fy = qy - (LOC + cy * CELLH);
    const float fz = qz - (LOC + cz * CELLH);
    const float gm = fmaxf(fmaxf(fmaxf(fx, CELLH - fx), fmaxf(fy, CELLH - fy)),
                           fmaxf(fz, CELLH - fz));

    float s0 = 3e38f, s1 = 3e38f, s2 = 3e38f;   // s = |p|^2 - 2 q.p  (= d^2 - qn)
    int   i0 = 0,     i1 = 0,     i2 = 0;

    for (int R = 0; R < GRID; R++) {
        const int zlo = max(cz - R, 0), zhi = min(cz + R, GRID - 1);
        const int z0  = zlo + ((zlo ^ sz) & 1);           // first z with z%2==sz
        for (int z = z0; z <= zhi; z += 2) {
            const bool zedge = (z == cz - R) || (z == cz + R);
            const int ylo = max(cy - R, 0), yhi = min(cy + R, GRID - 1);
            const int y0  = ylo + ((ylo ^ sy) & 1);       // first y with y%2==sy
            for (int y = y0; y <= yhi; y += 2) {
                const bool yedge = (y == cy - R) || (y == cy + R);
                const int rowbase = (z * GRID + y) * GRID;
                if (zedge || yedge) {
                    const int xlo = max(cx - R, 0), xhi = min(cx + R, GRID - 1);
                    const int start = g_cellstart[rowbase + xlo];
                    const int end   = g_cellstart[rowbase + xhi + 1];
                    for (int p = start; p < end; p++) {
                        float4 P = g_spts[p];
                        float s = fmaf(-2.0f,
                                       fmaf(qx, P.x, fmaf(qy, P.y, qz * P.z)), P.w);
                        bins3(s, p, s0, s1, s2, i0, i1, i2);
                    }
                } else {
                    #pragma unroll
                    for (int side = 0; side < 2; side++) {
                        int xc = side ? cx + R : cx - R;
                        if (xc < 0 || xc > GRID - 1) continue;
                        const int start = g_cellstart[rowbase + xc];
                        const int end   = g_cellstart[rowbase + xc + 1];
                        for (int p = start; p < end; p++) {
                            float4 P = g_spts[p];
                            float s = fmaf(-2.0f,
                                           fmaf(qx, P.x, fmaf(qy, P.y, qz * P.z)), P.w);
                            bins3(s, p, s0, s1, s2, i0, i1, i2);
                        }
                    }
                }
            }
        }
        // conservative per-split stop: partial s2 >= global s2, so never stops early
        float mind = (float)(R + 1) * CELLH - gm;
        if (mind > 0.0f && fmaf(mind, mind, -qn) >= s2) break;
    }

    sh_s[tl][0] = s0; sh_s[tl][1] = s1; sh_s[tl][2] = s2;
    sh_i[tl][0] = i0; sh_i[tl][1] = i1; sh_i[tl][2] = i2;
    __syncthreads();

    // first 64 threads merge the 4 splits of their query
    if (tl < QPB) {
        float m0 = 3e38f, m1 = 3e38f, m2 = 3e38f;
        int   j0 = 0,     j1 = 0,     j2 = 0;
        #pragma unroll
        for (int sp = 0; sp < 4; sp++) {
            int r = sp * QPB + tl;
            #pragma unroll
            for (int k = 0; k < 3; k++)
                bins3(sh_s[r][k], sh_i[r][k], m0, m1, m2, j0, j1, j2);
        }
        float d0 = fmaxf(m0 + qn, 0.0f);
        float d1 = fmaxf(m1 + qn, 0.0f);
        float d2 = fmaxf(m2 + qn, 0.0f);
        float r0 = 1.0f / (d0 + 1e-8f);
        float r1 = 1.0f / (d1 + 1e-8f);
        float r2 = 1.0f / (d2 + 1e-8f);
        float inv = 1.0f / (r0 + r1 + r2);
        g_knn_idx[0][m] = g_ptid[j0];
        g_knn_idx[1][m] = g_ptid[j1];
        g_knn_idx[2][m] = g_ptid[j2];
        g_knn_w[0][m] = r0 * inv;
        g_knn_w[1][m] = r1 * inv;
        g_knn_w[2][m] = r2 * inv;
    }
}

// ---------------- fp32 linear: out[M][128] = A[M][KTOT] @ W[128][KTOT]^T + b ----
// FUSE also re-zeros the grid count arrays for the next replay.
template<int BM, int KTOT, bool FUSE>
__global__ void __launch_bounds__(BM*2) linear_kernel(
    const float* __restrict__ A,
    const float* __restrict__ W,
    const float* __restrict__ bias,
    float* __restrict__ out)
{
    constexpr int BK   = 32;
    constexpr int NT   = BM * 2;
    constexpr int ASTR = BM + 4;
    __shared__ __align__(16) float As[BK][ASTR];
    __shared__ __align__(16) float Ws[BK][C_OUT + 4];

    const int tid = threadIdx.x;
    const int tx  = tid & 15;
    const int ty  = tid >> 4;
    const int rowBase = blockIdx.x * BM;

    if (FUSE) {
        int g = blockIdx.x * NT + tid;
        if (g < NC) { g_cellcnt[g] = 0; g_qcnt[g] = 0; }
    }

    u64 acc[8][4];
    #pragma unroll
    for (int i = 0; i < 8; i++)
        #pragma unroll
        for (int j = 0; j < 4; j++) acc[i][j] = 0ull;

    for (int k0 = 0; k0 < KTOT; k0 += BK) {
        #pragma unroll
        for (int i = tid; i < BM * (BK/4); i += NT) {
            int r  = i >> 3;
            int kq = (i & 7) << 2;
            float4 v = *(const float4*)(A + (size_t)(rowBase + r) * KTOT + k0 + kq);
            As[kq+0][r] = v.x; As[kq+1][r] = v.y; As[kq+2][r] = v.z; As[kq+3][r] = v.w;
        }
        #pragma unroll
        for (int i = tid; i < C_OUT * (BK/4); i += NT) {
            int c  = i >> 3;
            int kq = (i & 7) << 2;
            float4 v = *(const float4*)(W + (size_t)c * KTOT + k0 + kq);
            Ws[kq+0][c] = v.x; Ws[kq+1][c] = v.y; Ws[kq+2][c] = v.z; Ws[kq+3][c] = v.w;
        }
        __syncthreads();
        #pragma unroll
        for (int k = 0; k < BK; k++) {
            float4 alo = *(const float4*)&As[k][ty*8];
            float4 ahi = *(const float4*)&As[k][ty*8 + 4];
            ulonglong2 w01 = *(const ulonglong2*)&Ws[k][tx*8];
            ulonglong2 w23 = *(const ulonglong2*)&Ws[k][tx*8 + 4];
            u64 wv[4] = {w01.x, w01.y, w23.x, w23.y};
            u64 a2[8];
            a2[0] = splat2(alo.x); a2[1] = splat2(alo.y);
            a2[2] = splat2(alo.z); a2[3] = splat2(alo.w);
            a2[4] = splat2(ahi.x); a2[5] = splat2(ahi.y);
            a2[6] = splat2(ahi.z); a2[7] = splat2(ahi.w);
            #pragma unroll
            for (int i = 0; i < 8; i++)
                #pragma unroll
                for (int j = 0; j < 4; j++)
                    fma2(acc[i][j], a2[i], wv[j]);
        }
        __syncthreads();
    }

    const int cb = tx * 8;
    float b[8];
    #pragma unroll
    for (int j = 0; j < 8; j++) b[j] = bias[cb + j];

    #pragma unroll
    for (int i = 0; i < 8; i++) {
        const int m = rowBase + ty*8 + i;
        float o[8];
        #pragma unroll
        for (int j = 0; j < 4; j++) {
            U64F2 cvt; cvt.u = acc[i][j];
            o[2*j]   = cvt.f.x + b[2*j];
            o[2*j+1] = cvt.f.y + b[2*j+1];
        }
        if (FUSE) {
            #pragma unroll
            for (int t = 0; t < 3; t++) {
                int   idx = g_knn_idx[t][m];
                float w   = g_knn_w[t][m];
                const float* fr = g_downf + (size_t)idx * C_OUT + cb;
                float4 glo = *(const float4*)fr;
                float4 ghi = *(const float4*)(fr + 4);
                o[0] = fmaf(w, glo.x, o[0]); o[1] = fmaf(w, glo.y, o[1]);
                o[2] = fmaf(w, glo.z, o[2]); o[3] = fmaf(w, glo.w, o[3]);
                o[4] = fmaf(w, ghi.x, o[4]); o[5] = fmaf(w, ghi.y, o[5]);
                o[6] = fmaf(w, ghi.z, o[6]); o[7] = fmaf(w, ghi.w, o[7]);
            }
        }
        *(float4*)(out + (size_t)m * C_OUT + cb)     = make_float4(o[0], o[1], o[2], o[3]);
        *(float4*)(out + (size_t)m * C_OUT + cb + 4) = make_float4(o[4], o[5], o[6], o[7]);
    }
}

// ---------------- launch (ncu profiles launch #4 = knn_grid) ----------------
extern "C" void kernel_launch(void* const* d_in, const int* in_sizes, int n_in,
                              void* d_out, int out_size) {
    (void)in_sizes; (void)n_in; (void)out_size;
    const float* up_points     = (const float*)d_in[0];
    const float* up_features   = (const float*)d_in[1];
    const float* down_points   = (const float*)d_in[2];
    const float* down_features = (const float*)d_in[3];
    const float* W_up          = (const float*)d_in[4];
    const float* b_up          = (const float*)d_in[5];
    const float* W_down        = (const float*)d_in[6];
    const float* b_down        = (const float*)d_in[7];
    float* out = (float*)d_out;

    float* downf_ptr = nullptr;
    cudaGetSymbolAddress((void**)&downf_ptr, g_downf);
    cudaFuncSetAttribute(scan_kernel, cudaFuncAttributeMaxDynamicSharedMemorySize,
                         SCAN_SMEM_BYTES);

    hist_kernel<<<(N_DOWN + M_UP + 255) / 256, 256>>>(down_points, up_points);      // 1
    scan_kernel<<<1, 1024, SCAN_SMEM_BYTES>>>();                                     // 2
    scatter_kernel<<<(N_DOWN + M_UP + 255) / 256, 256>>>(down_points, up_points);    // 3
    knn_grid_kernel<<<M_UP / QPB, 256>>>(up_points);                                 // 4 <- profiled
    linear_kernel<64, 256, false><<<N_DOWN / 64, 128>>>(down_features, W_down, b_down, downf_ptr); // 5
    linear_kernel<64, 128, true><<<M_UP / 64, 128>>>(up_features, W_up, b_up, out);  // 6
}